// round 9
// baseline (speedup 1.0000x reference)
#include <cuda_runtime.h>
#include <math.h>

#define TT 2048
#define BB 64
#define DD 256
#define HH 512

#define NGROUPS 8
#define GC 16         // CTAs per group
#define GB 8          // batch elems per group
#define JC 32         // output columns owned per CTA
#define NT 256        // 8 warps
#define HPAD 12       // hbuf row pad (16B-aligned rows, conflict-free LDS.128)

// ---------------- packed fp32x2 helpers ----------------
#define FMA_X2(d, a, b, c) \
    asm("fma.rn.f32x2 %0, %1, %2, %3;" : "=l"(d) : "l"(a), "l"(b), "l"(c))
#define ADD_X2(d, a, b) \
    asm("add.rn.f32x2 %0, %1, %2;" : "=l"(d) : "l"(a), "l"(b))
#define DUP_X2(d, s) \
    asm("mov.b64 %0, {%1, %1};" : "=l"(d) : "r"(__float_as_uint(s)))
#define UNPACK_X2(lo, hi, p) \
    asm("mov.b64 {%0, %1}, %2;" : "=r"(lo), "=r"(hi) : "l"(p))

// ---------------- device scratch ----------------
__device__ float g_Gx[(size_t)TT * 3 * BB * HH];
__device__ float g_h[BB * HH];
__device__ float g_rh[BB * HH];
__device__ unsigned g_bcnt[NGROUPS];
__device__ unsigned g_bgen[NGROUPS];

// ---------------- split arrive/wait barrier (generation-based, replay-safe) ---------
// arrive: capture gen (== value before this barrier's release), add; last releases.
// wait:   poll until gen changes. Monotonic gen -> safe across graph replays.
__device__ __forceinline__ unsigned bar_arrive(int grp) {
    __syncthreads();
    unsigned gen = 0;
    if (threadIdx.x == 0) {
        asm volatile("ld.acquire.gpu.global.u32 %0, [%1];"
                     : "=r"(gen) : "l"(&g_bgen[grp]));
        unsigned old;
        asm volatile("atom.acq_rel.gpu.global.add.u32 %0, [%1], %2;"
                     : "=r"(old) : "l"(&g_bcnt[grp]), "r"(1u));
        if (old == GC - 1u) {
            asm volatile("st.relaxed.gpu.global.u32 [%0], %1;"
                         :: "l"(&g_bcnt[grp]), "r"(0u));
            asm volatile("st.release.gpu.global.u32 [%0], %1;"
                         :: "l"(&g_bgen[grp]), "r"(gen + 1u));
        }
    }
    return gen;
}
__device__ __forceinline__ void bar_wait(int grp, unsigned gen) {
    if (threadIdx.x == 0) {
        unsigned cur;
        do {
            asm volatile("ld.acquire.gpu.global.u32 %0, [%1];"
                         : "=r"(cur) : "l"(&g_bgen[grp]));
        } while (cur == gen);
    }
    __syncthreads();
}

// =====================================================================================
// Phase 1 (unchanged, proven): Gx[t][gate][b][j] = x[t,b,:] @ Wg[0:256,:] + bg
// =====================================================================================
__global__ void __launch_bounds__(256) phase1_gemm(
    const float* __restrict__ x,
    const float* __restrict__ Wz, const float* __restrict__ bz,
    const float* __restrict__ Wr, const float* __restrict__ br,
    const float* __restrict__ Wh, const float* __restrict__ bh)
{
    __shared__ float xs[32 * 132];
    __shared__ float ws[32 * 64];

    const int gate = blockIdx.y >> 3;
    const int jt0  = (blockIdx.y & 7) * 64;
    const float* W    = (gate == 0) ? Wz : ((gate == 1) ? Wr : Wh);
    const float* bias = (gate == 0) ? bz : ((gate == 1) ? br : bh);
    const int m0  = blockIdx.x * 128;
    const int tid = threadIdx.x;
    const int tn = tid & 15;
    const int tm = tid >> 4;

    unsigned long long pa[4][4];
#pragma unroll
    for (int i = 0; i < 4; i++)
#pragma unroll
        for (int j = 0; j < 4; j++) pa[i][j] = 0ull;

    for (int kc = 0; kc < 8; kc++) {
#pragma unroll
        for (int i = 0; i < 16; i++) {
            int idx = tid + i * 256;
            int row = idx >> 5, kk = idx & 31;
            xs[kk * 132 + row] = x[(size_t)(m0 + row) * DD + kc * 32 + kk];
        }
#pragma unroll
        for (int i = 0; i < 8; i++) {
            int idx = tid + i * 256;
            int kk = idx >> 6, jj = idx & 63;
            ws[kk * 64 + jj] = W[(size_t)(kc * 32 + kk) * HH + jt0 + jj];
        }
        __syncthreads();
#pragma unroll 8
        for (int kk = 0; kk < 32; kk++) {
            float4 w4 = *(const float4*)&ws[kk * 64 + tn * 4];
            ulonglong2 xL = *(const ulonglong2*)&xs[kk * 132 + tm * 8];
            ulonglong2 xH = *(const ulonglong2*)&xs[kk * 132 + tm * 8 + 4];
            unsigned long long hp[4] = {xL.x, xL.y, xH.x, xH.y};
            unsigned long long wd[4];
            DUP_X2(wd[0], w4.x); DUP_X2(wd[1], w4.y);
            DUP_X2(wd[2], w4.z); DUP_X2(wd[3], w4.w);
#pragma unroll
            for (int i = 0; i < 4; i++)
#pragma unroll
                for (int j = 0; j < 4; j++)
                    FMA_X2(pa[i][j], hp[i], wd[j], pa[i][j]);
        }
        __syncthreads();
    }

#pragma unroll
    for (int i = 0; i < 4; i++) {
#pragma unroll
        for (int j = 0; j < 4; j++) {
            unsigned lo, hi;
            UNPACK_X2(lo, hi, pa[i][j]);
            float bj = bias[jt0 + tn * 4 + j];
            int mA = m0 + tm * 8 + 2 * i;
            int tA = mA >> 6, bA = mA & 63;
            g_Gx[(((size_t)tA * 3 + gate) * BB + bA) * HH + jt0 + tn * 4 + j] =
                __uint_as_float(lo) + bj;
            int mB = mA + 1;
            int tB = mB >> 6, bB = mB & 63;
            g_Gx[(((size_t)tB * 3 + gate) * BB + bB) * HH + jt0 + tn * 4 + j] =
                __uint_as_float(hi) + bj;
        }
    }
}

// =====================================================================================
// Phase 2: persistent GRU. 128 CTAs = 8 groups x 16. NT=256 (8 warps).
// Uniform dot mapping (R5 stage-2 proven): warp w -> khalf=w>>2 (K/2), jt=w&3 (8 cols).
// Per-step order: fill(h) | r-dot -> combine -> store rh -> ARRIVE | z-dot |
// WAIT -> issue rh LDGs -> z-combine -> STS -> h~-dot -> combine -> update -> ARRIVE/WAIT.
// Barrier-1 round trip hidden under the z-dot; fill-2 latency hidden under z-epilogue.
// =====================================================================================
struct DotOut { unsigned long long v; };

__global__ void __launch_bounds__(NT, 1) phase2_gru(
    const float* __restrict__ h0in,
    const float* __restrict__ Wz,
    const float* __restrict__ Wr,
    const float* __restrict__ Wh,
    float* __restrict__ out)
{
    extern __shared__ float sm[];
    float* wzs  = sm;                     // [512][32] swizzled
    float* wrs  = wzs + HH * JC;
    float* whs  = wrs + HH * JC;
    float* hbuf = whs + HH * JC;          // [512][HPAD]
    float* z_s  = hbuf + HH * HPAD;       // [8][32]
    float* ho_s = z_s + GB * JC;          // [8][32]
    unsigned long long* partU = (unsigned long long*)(ho_s + GB * JC);  // [4][32]

    const int grp  = blockIdx.x >> 4;
    const int rank = blockIdx.x & 15;
    const int b0 = grp * GB;
    const int j0 = rank * JC;
    const int tid  = threadIdx.x;
    const int warp = tid >> 5;
    const int lane = tid & 31;

    // resident recurrent weights (rows DD..DD+511), float4-slot XOR swizzle
    for (int idx = tid; idx < HH * JC; idx += NT) {
        int k = idx >> 5, jl = idx & 31;
        int phys = k * JC + ((((jl >> 2) ^ (k & 7))) << 2) + (jl & 3);
        size_t goff = (size_t)(DD + k) * HH + j0 + jl;
        wzs[phys] = Wz[goff];
        wrs[phys] = Wr[goff];
        whs[phys] = Wh[goff];
    }
    __syncthreads();

    const int khalf = warp >> 2;                 // K/2 half
    const int jt    = warp & 3;                  // 8-col tile
    const int slotA = (jt * 2) ^ (lane & 7);
    const int slotB = (jt * 2 + 1) ^ (lane & 7);
    const int bp    = lane >> 3;                 // owned b-pair
    const int jl_o  = jt * 8 + (lane & 7);       // owned column
    const int fb    = tid >> 5;                  // fill: batch row = warp
    const int fk    = tid & 31;                  // fill: k quad index base

    for (int t = 0; t < TT; t++) {
        // ---------------- fill hbuf with h (vectorized, coalesced) ----------------
        const float* hsrc = (t == 0) ? h0in : (const float*)g_h;
        {
            float4 hv[4];
#pragma unroll
            for (int o = 0; o < 4; o++)
                hv[o] = __ldcg((const float4*)&hsrc[(size_t)(b0 + fb) * HH + (o * 32 + fk) * 4]);
#pragma unroll
            for (int o = 0; o < 4; o++) {
                int k = (o * 32 + fk) * 4;
                hbuf[(k + 0) * HPAD + fb] = hv[o].x;
                hbuf[(k + 1) * HPAD + fb] = hv[o].y;
                hbuf[(k + 2) * HPAD + fb] = hv[o].z;
                hbuf[(k + 3) * HPAD + fb] = hv[o].w;
            }
        }
        __syncthreads();

        // stash h_old for own columns
        { int b = tid >> 5, jl = tid & 31; ho_s[tid] = hbuf[(j0 + jl) * HPAD + b]; }

        // Gx prefetch (epilogue = khalf 0 warps); gates: 0=z, 1=r, 2=h
        float gxr0 = 0.f, gxr1 = 0.f, gxz0 = 0.f, gxz1 = 0.f, gx20 = 0.f, gx21 = 0.f;
        if (khalf == 0) {
            size_t rr = (((size_t)t * 3 + 1) * BB + b0 + 2 * bp) * HH + j0 + jl_o;
            gxr0 = __ldg(&g_Gx[rr]);       gxr1 = __ldg(&g_Gx[rr + HH]);
            size_t rz = (((size_t)t * 3 + 0) * BB + b0 + 2 * bp) * HH + j0 + jl_o;
            gxz0 = __ldg(&g_Gx[rz]);       gxz1 = __ldg(&g_Gx[rz + HH]);
            size_t rh2 = (((size_t)t * 3 + 2) * BB + b0 + 2 * bp) * HH + j0 + jl_o;
            gx20 = __ldg(&g_Gx[rh2]);      gx21 = __ldg(&g_Gx[rh2 + HH]);
        }

        unsigned long long a2[32];

        // ================= r-dot (K/2 per warp) =================
#pragma unroll
        for (int v = 0; v < 32; v++) a2[v] = 0ull;
        {
            const int k0 = khalf * 256 + lane;
            const float4* wp = (const float4*)(wrs + k0 * JC);
            const char*   hp = (const char*)(hbuf + k0 * HPAD);
#pragma unroll
            for (int i = 0; i < 8; i++) {
                float4 w0 = wp[slotA], w1 = wp[slotB];
                ulonglong2 hL = *(const ulonglong2*)hp;
                ulonglong2 hH = *(const ulonglong2*)(hp + 16);
                unsigned long long hb[4] = {hL.x, hL.y, hH.x, hH.y};
                unsigned long long wd[8];
                DUP_X2(wd[0], w0.x); DUP_X2(wd[1], w0.y);
                DUP_X2(wd[2], w0.z); DUP_X2(wd[3], w0.w);
                DUP_X2(wd[4], w1.x); DUP_X2(wd[5], w1.y);
                DUP_X2(wd[6], w1.z); DUP_X2(wd[7], w1.w);
#pragma unroll
                for (int p = 0; p < 4; p++)
#pragma unroll
                    for (int j = 0; j < 8; j++)
                        FMA_X2(a2[p * 8 + j], hb[p], wd[j], a2[p * 8 + j]);
                wp += 32 * JC / 4;
                hp += 32 * HPAD * 4;
            }
        }
#pragma unroll
        for (int s = 0; s < 5; s++) {
            const int m = 16 >> s, half = 16 >> s;
            bool up = (lane & m) != 0;
#pragma unroll
            for (int i = 0; i < half; i++) {
                unsigned long long send = up ? a2[i] : a2[i + half];
                unsigned long long r = __shfl_xor_sync(0xffffffffu, send, m);
                unsigned long long keep = up ? a2[i + half] : a2[i];
                ADD_X2(a2[i], keep, r);
            }
        }
        if (khalf == 1) partU[jt * 32 + lane] = a2[0];
        __syncthreads();
        if (khalf == 0) {
            unsigned long long tot;
            ADD_X2(tot, a2[0], partU[jt * 32 + lane]);
            unsigned lo, hi;
            UNPACK_X2(lo, hi, tot);
            float p0 = __uint_as_float(lo) + gxr0;
            float p1 = __uint_as_float(hi) + gxr1;
            float s0 = 1.f / (1.f + __expf(-p0));
            float s1 = 1.f / (1.f + __expf(-p1));
            int bA = 2 * bp, bB = 2 * bp + 1;
            float rh0 = s0 * hbuf[(j0 + jl_o) * HPAD + bA];
            float rh1 = s1 * hbuf[(j0 + jl_o) * HPAD + bB];
            __stcg(&g_rh[(size_t)(b0 + bA) * HH + j0 + jl_o], rh0);
            __stcg(&g_rh[(size_t)(b0 + bB) * HH + j0 + jl_o], rh1);
        }

        unsigned genR = bar_arrive(grp);   // rh published; round trip hidden below

        // ================= z-dot (hides barrier-1 round trip) =================
#pragma unroll
        for (int v = 0; v < 32; v++) a2[v] = 0ull;
        {
            const int k0 = khalf * 256 + lane;
            const float4* wp = (const float4*)(wzs + k0 * JC);
            const char*   hp = (const char*)(hbuf + k0 * HPAD);
#pragma unroll
            for (int i = 0; i < 8; i++) {
                float4 w0 = wp[slotA], w1 = wp[slotB];
                ulonglong2 hL = *(const ulonglong2*)hp;
                ulonglong2 hH = *(const ulonglong2*)(hp + 16);
                unsigned long long hb[4] = {hL.x, hL.y, hH.x, hH.y};
                unsigned long long wd[8];
                DUP_X2(wd[0], w0.x); DUP_X2(wd[1], w0.y);
                DUP_X2(wd[2], w0.z); DUP_X2(wd[3], w0.w);
                DUP_X2(wd[4], w1.x); DUP_X2(wd[5], w1.y);
                DUP_X2(wd[6], w1.z); DUP_X2(wd[7], w1.w);
#pragma unroll
                for (int p = 0; p < 4; p++)
#pragma unroll
                    for (int j = 0; j < 8; j++)
                        FMA_X2(a2[p * 8 + j], hb[p], wd[j], a2[p * 8 + j]);
                wp += 32 * JC / 4;
                hp += 32 * HPAD * 4;
            }
        }
#pragma unroll
        for (int s = 0; s < 5; s++) {
            const int m = 16 >> s, half = 16 >> s;
            bool up = (lane & m) != 0;
#pragma unroll
            for (int i = 0; i < half; i++) {
                unsigned long long send = up ? a2[i] : a2[i + half];
                unsigned long long r = __shfl_xor_sync(0xffffffffu, send, m);
                unsigned long long keep = up ? a2[i + half] : a2[i];
                ADD_X2(a2[i], keep, r);
            }
        }
        if (khalf == 1) partU[jt * 32 + lane] = a2[0];
        __syncthreads();

        bar_wait(grp, genR);   // rh ready group-wide (mostly already released)

        // issue rh loads immediately (latency hidden under z-epilogue)
        float4 rv[4];
#pragma unroll
        for (int o = 0; o < 4; o++)
            rv[o] = __ldcg((const float4*)&g_rh[(size_t)(b0 + fb) * HH + (o * 32 + fk) * 4]);

        // z combine + sigmoid -> z_s
        if (khalf == 0) {
            unsigned long long tot;
            ADD_X2(tot, a2[0], partU[jt * 32 + lane]);
            unsigned lo, hi;
            UNPACK_X2(lo, hi, tot);
            float p0 = __uint_as_float(lo) + gxz0;
            float p1 = __uint_as_float(hi) + gxz1;
            int bA = 2 * bp, bB = 2 * bp + 1;
            z_s[bA * JC + jl_o] = 1.f / (1.f + __expf(-p0));
            z_s[bB * JC + jl_o] = 1.f / (1.f + __expf(-p1));
        }

        // STS rh into hbuf
#pragma unroll
        for (int o = 0; o < 4; o++) {
            int k = (o * 32 + fk) * 4;
            hbuf[(k + 0) * HPAD + fb] = rv[o].x;
            hbuf[(k + 1) * HPAD + fb] = rv[o].y;
            hbuf[(k + 2) * HPAD + fb] = rv[o].z;
            hbuf[(k + 3) * HPAD + fb] = rv[o].w;
        }
        __syncthreads();

        // ================= h~-dot (K/2 per warp) =================
#pragma unroll
        for (int v = 0; v < 32; v++) a2[v] = 0ull;
        {
            const int k0 = khalf * 256 + lane;
            const float4* wp = (const float4*)(whs + k0 * JC);
            const char*   hp = (const char*)(hbuf + k0 * HPAD);
#pragma unroll
            for (int i = 0; i < 8; i++) {
                float4 w0 = wp[slotA], w1 = wp[slotB];
                ulonglong2 hL = *(const ulonglong2*)hp;
                ulonglong2 hH = *(const ulonglong2*)(hp + 16);
                unsigned long long hb[4] = {hL.x, hL.y, hH.x, hH.y};
                unsigned long long wd[8];
                DUP_X2(wd[0], w0.x); DUP_X2(wd[1], w0.y);
                DUP_X2(wd[2], w0.z); DUP_X2(wd[3], w0.w);
                DUP_X2(wd[4], w1.x); DUP_X2(wd[5], w1.y);
                DUP_X2(wd[6], w1.z); DUP_X2(wd[7], w1.w);
#pragma unroll
                for (int p = 0; p < 4; p++)
#pragma unroll
                    for (int j = 0; j < 8; j++)
                        FMA_X2(a2[p * 8 + j], hb[p], wd[j], a2[p * 8 + j]);
                wp += 32 * JC / 4;
                hp += 32 * HPAD * 4;
            }
        }
#pragma unroll
        for (int s = 0; s < 5; s++) {
            const int m = 16 >> s, half = 16 >> s;
            bool up = (lane & m) != 0;
#pragma unroll
            for (int i = 0; i < half; i++) {
                unsigned long long send = up ? a2[i] : a2[i + half];
                unsigned long long r = __shfl_xor_sync(0xffffffffu, send, m);
                unsigned long long keep = up ? a2[i + half] : a2[i];
                ADD_X2(a2[i], keep, r);
            }
        }
        if (khalf == 1) partU[jt * 32 + lane] = a2[0];
        __syncthreads();
        if (khalf == 0) {
            unsigned long long tot;
            ADD_X2(tot, a2[0], partU[jt * 32 + lane]);
            unsigned lo, hi;
            UNPACK_X2(lo, hi, tot);
            int bA = 2 * bp, bB = 2 * bp + 1;
            float ht0 = tanhf(__uint_as_float(lo) + gx20);
            float ht1 = tanhf(__uint_as_float(hi) + gx21);
            float z0 = z_s[bA * JC + jl_o], z1 = z_s[bB * JC + jl_o];
            float o0 = ho_s[bA * JC + jl_o], o1 = ho_s[bB * JC + jl_o];
            float hn0 = o0 + z0 * (ht0 - o0);
            float hn1 = o1 + z1 * (ht1 - o1);
            __stcg(&g_h[(size_t)(b0 + bA) * HH + j0 + jl_o], hn0);
            __stcg(&g_h[(size_t)(b0 + bB) * HH + j0 + jl_o], hn1);
            out[((size_t)t * BB + b0 + bA) * HH + j0 + jl_o] = hn0;
            out[((size_t)t * BB + b0 + bB) * HH + j0 + jl_o] = hn1;
        }

        unsigned genH = bar_arrive(grp);
        bar_wait(grp, genH);   // h complete before next step
    }
}

// =====================================================================================
extern "C" void kernel_launch(void* const* d_in, const int* in_sizes, int n_in,
                              void* d_out, int out_size)
{
    const float* x  = (const float*)d_in[0];
    const float* h0 = (const float*)d_in[1];
    const float* Wz = (const float*)d_in[2];
    const float* bz = (const float*)d_in[3];
    const float* Wr = (const float*)d_in[4];
    const float* br = (const float*)d_in[5];
    const float* Wh = (const float*)d_in[6];
    const float* bh = (const float*)d_in[7];
    float* out = (float*)d_out;

    const int smem_bytes = (3 * HH * JC + HH * HPAD + 2 * GB * JC) * (int)sizeof(float)
                         + 4 * 32 * (int)sizeof(unsigned long long);
    cudaFuncSetAttribute(phase2_gru, cudaFuncAttributeMaxDynamicSharedMemorySize, smem_bytes);

    dim3 g1((TT * BB) / 128, 24);
    phase1_gemm<<<g1, 256>>>(x, Wz, bz, Wr, br, Wh, bh);

    phase2_gru<<<NGROUPS * GC, NT, smem_bytes>>>(h0, Wz, Wr, Wh, out);
}